// round 1
// baseline (speedup 1.0000x reference)
#include <cuda_runtime.h>

#define NV 5
#define NB 2
#define NC 32
#define NH 256
#define NW 320
#define HW (NH*NW)
#define CN 4

// Per (b, view-1): 9 rotation + 3 translation floats of proj_i @ inv(proj_0)
__device__ float g_proj[NB*(NV-1)*12];

__global__ void setup_proj_kernel(const float* __restrict__ pm) {
    int t = threadIdx.x;
    if (t >= NB*(NV-1)) return;
    int b  = t / (NV-1);
    int vi = t % (NV-1) + 1;

    double M0[3][3], m0[3], Mi[3][3], mi[3];
    // build_proj: top3x4 = K(3x3) @ E[:3,:4]
    for (int which = 0; which < 2; which++) {
        int v = (which == 0) ? 0 : vi;
        const float* E = pm + ((size_t)(b*NV + v)*2 + 0)*16;
        const float* K = pm + ((size_t)(b*NV + v)*2 + 1)*16;
        double (*M)[3] = (which == 0) ? M0 : Mi;
        double *m      = (which == 0) ? m0 : mi;
        for (int r = 0; r < 3; r++) {
            for (int c = 0; c < 3; c++) {
                double s = 0;
                for (int k = 0; k < 3; k++) s += (double)K[r*4+k] * (double)E[k*4+c];
                M[r][c] = s;
            }
            double s = 0;
            for (int k = 0; k < 3; k++) s += (double)K[r*4+k] * (double)E[k*4+3];
            m[r] = s;
        }
    }
    // 3x3 inverse of M0 (bottom row of full 4x4 is [0,0,0,1], so full inverse
    // reduces to [[M0^-1, -M0^-1 m0],[0,1]])
    double a00=M0[0][0],a01=M0[0][1],a02=M0[0][2];
    double a10=M0[1][0],a11=M0[1][1],a12=M0[1][2];
    double a20=M0[2][0],a21=M0[2][1],a22=M0[2][2];
    double det = a00*(a11*a22-a12*a21) - a01*(a10*a22-a12*a20) + a02*(a10*a21-a11*a20);
    double id = 1.0/det;
    double I[3][3];
    I[0][0]=(a11*a22-a12*a21)*id; I[0][1]=(a02*a21-a01*a22)*id; I[0][2]=(a01*a12-a02*a11)*id;
    I[1][0]=(a12*a20-a10*a22)*id; I[1][1]=(a00*a22-a02*a20)*id; I[1][2]=(a02*a10-a00*a12)*id;
    I[2][0]=(a10*a21-a11*a20)*id; I[2][1]=(a01*a20-a00*a21)*id; I[2][2]=(a00*a11-a01*a10)*id;

    double R[3][3], tv[3];
    for (int r = 0; r < 3; r++)
        for (int c = 0; c < 3; c++) {
            double s = 0;
            for (int k = 0; k < 3; k++) s += Mi[r][k]*I[k][c];
            R[r][c] = s;
        }
    for (int r = 0; r < 3; r++) {
        double s = 0;
        for (int k = 0; k < 3; k++) s += R[r][k]*m0[k];
        tv[r] = mi[r] - s;
    }
    float* o = g_proj + t*12;
    o[0]=(float)R[0][0]; o[1]=(float)R[0][1]; o[2]=(float)R[0][2];
    o[3]=(float)R[1][0]; o[4]=(float)R[1][1]; o[5]=(float)R[1][2];
    o[6]=(float)R[2][0]; o[7]=(float)R[2][1]; o[8]=(float)R[2][2];
    o[9]=(float)tv[0]; o[10]=(float)tv[1]; o[11]=(float)tv[2];
}

__global__ void __launch_bounds__(256)
getcost_kernel(const float* __restrict__ feat,
               const float* __restrict__ dvals,
               const float* __restrict__ dint,
               const float* __restrict__ vwts,
               float* __restrict__ out)
{
    int pix = blockIdx.x * 256 + threadIdx.x;
    int b = pix / HW;
    int p = pix - b*HW;
    int yy = p / NW;
    int xx = p - yy*NW;
    float fx = (float)xx, fy = (float)yy;

    float invd = 1.0f / dvals[pix];
    float itv  = dint[pix];
    float low  = invd - (CN*0.5f)*itv;
    float step = (CN * itv) / (float)(CN - 1);

    float z[CN];
#pragma unroll
    for (int d = 0; d < CN; d++) z[d] = 1.0f / (low + (float)d*step);

    // reference-view features for this pixel
    float ref[NC];
    const float* rbase = feat + (size_t)b*NC*HW + p;
#pragma unroll
    for (int c = 0; c < NC; c++) ref[c] = __ldg(rbase + (size_t)c*HW);

    float vol[CN] = {0.f, 0.f, 0.f, 0.f};
    float wsum = 1e-5f;

    for (int vi = 1; vi < NV; vi++) {
        const float* PR = g_proj + ((size_t)b*(NV-1) + (vi-1))*12;
        float r00=PR[0], r01=PR[1], r02=PR[2];
        float r10=PR[3], r11=PR[4], r12=PR[5];
        float r20=PR[6], r21=PR[7], r22=PR[8];
        float t0 =PR[9], t1 =PR[10], t2 =PR[11];

        float u0 = r00*fx + r01*fy + r02;
        float u1 = r10*fx + r11*fy + r12;
        float u2 = r20*fx + r21*fy + r22;

        float vw = __ldg(vwts + ((size_t)b*(NV-1) + (vi-1))*HW + p);

        int   idx[CN][4];
        float w  [CN][4];
#pragma unroll
        for (int d = 0; d < CN; d++) {
            float px = u0*z[d] + t0;
            float py = u1*z[d] + t1;
            float pz = u2*z[d] + t2;
            float gx = px / pz;
            float gy = py / pz;
            float x0 = floorf(gx), y0 = floorf(gy);
            float wx = gx - x0,    wy = gy - y0;
            float x1 = x0 + 1.0f,  y1 = y0 + 1.0f;

            bool vx0 = (x0 >= 0.0f) && (x0 <= (float)(NW-1));
            bool vx1 = (x1 >= 0.0f) && (x1 <= (float)(NW-1));
            bool vy0 = (y0 >= 0.0f) && (y0 <= (float)(NH-1));
            bool vy1 = (y1 >= 0.0f) && (y1 <= (float)(NH-1));

            int xi0 = (int)fminf(fmaxf(x0, 0.0f), (float)(NW-1));
            int xi1 = (int)fminf(fmaxf(x1, 0.0f), (float)(NW-1));
            int yi0 = (int)fminf(fmaxf(y0, 0.0f), (float)(NH-1));
            int yi1 = (int)fminf(fmaxf(y1, 0.0f), (float)(NH-1));

            idx[d][0] = yi0*NW + xi0;
            idx[d][1] = yi0*NW + xi1;
            idx[d][2] = yi1*NW + xi0;
            idx[d][3] = yi1*NW + xi1;

            float iwx = 1.0f - wx, iwy = 1.0f - wy;
            w[d][0] = (vx0 && vy0) ? iwx*iwy : 0.0f;
            w[d][1] = (vx1 && vy0) ? wx*iwy  : 0.0f;
            w[d][2] = (vx0 && vy1) ? iwx*wy  : 0.0f;
            w[d][3] = (vx1 && vy1) ? wx*wy   : 0.0f;
        }

        float S[CN][4];
#pragma unroll
        for (int d = 0; d < CN; d++)
#pragma unroll
            for (int k = 0; k < 4; k++) S[d][k] = 0.0f;

        const float* fb = feat + (size_t)(vi*NB + b)*NC*HW;
#pragma unroll 4
        for (int c = 0; c < NC; c++) {
            const float* fc = fb + (size_t)c*HW;
            float r = ref[c];
#pragma unroll
            for (int d = 0; d < CN; d++) {
                S[d][0] += r * __ldg(fc + idx[d][0]);
                S[d][1] += r * __ldg(fc + idx[d][1]);
                S[d][2] += r * __ldg(fc + idx[d][2]);
                S[d][3] += r * __ldg(fc + idx[d][3]);
            }
        }

#pragma unroll
        for (int d = 0; d < CN; d++) {
            float val = w[d][0]*S[d][0] + w[d][1]*S[d][1]
                      + w[d][2]*S[d][2] + w[d][3]*S[d][3];
            vol[d] += vw * val;
        }
        wsum += vw;
    }

    float scale = 1.0f / ((float)NC * wsum);   // mean over C folded with /wsum
#pragma unroll
    for (int d = 0; d < CN; d++) {
        float sim = vol[d] * scale;
        float* ob = out + ((size_t)b*NC*CN + d)*HW + p;
#pragma unroll
        for (int c = 0; c < NC; c++) ob[(size_t)c*CN*HW] = sim;
    }
}

extern "C" void kernel_launch(void* const* d_in, const int* in_sizes, int n_in,
                              void* d_out, int out_size) {
    // Identify inputs by size (robust to metadata ordering of scalars):
    //   features      = NV*NB*NC*HW
    //   proj_matrices = NB*NV*2*16
    //   view_weights  = NB*(NV-1)*HW
    //   depth_values / depth_interval = NB*HW each (depth_values first)
    const float *feat = nullptr, *projm = nullptr, *vw = nullptr;
    const float *dv = nullptr, *di = nullptr;
    const int sz_feat = NV*NB*NC*HW;
    const int sz_proj = NB*NV*2*16;
    const int sz_vw   = NB*(NV-1)*HW;
    const int sz_map  = NB*HW;
    for (int i = 0; i < n_in; i++) {
        int s = in_sizes[i];
        if (s == sz_feat)            feat  = (const float*)d_in[i];
        else if (s == sz_proj)       projm = (const float*)d_in[i];
        else if (s == sz_vw)         vw    = (const float*)d_in[i];
        else if (s == sz_map) {
            if (!dv) dv = (const float*)d_in[i];
            else if (!di) di = (const float*)d_in[i];
        }
    }
    float* out = (float*)d_out;

    setup_proj_kernel<<<1, 32>>>(projm);
    getcost_kernel<<<(NB*HW)/256, 256>>>(feat, dv, di, vw, out);
}